// round 3
// baseline (speedup 1.0000x reference)
#include <cuda_runtime.h>
#include <cuda_bf16.h>

// ---------------- problem constants ----------------
#define NA 500000
static const int H_DEG_CNT[7] = {20000, 80000, 150000, 150000, 75000, 20000, 5000};
static const int H_DEG_OFF[8] = {0, 20000, 100000, 250000, 400000, 475000, 495000, 500000};

// ---------------- scratch (device globals; no allocation allowed) ----------------
__device__ float    g_h1[(size_t)NA * 64];
__device__ float    g_h2[(size_t)NA * 64];
__device__ float    g_gsum[1024 * 128];
__device__ unsigned g_gmax[1024 * 128];

// ---------------- helpers ----------------
__device__ __forceinline__ unsigned enc_f(float f) {
    unsigned u = __float_as_uint(f);
    return (u >> 31) ? ~u : (u | 0x80000000u);
}
__device__ __forceinline__ float dec_f(unsigned u) {
    return (u >> 31) ? __uint_as_float(u & 0x7FFFFFFFu) : __uint_as_float(~u);
}
__device__ __forceinline__ float tanh_fast(float x) {
    float y;
    asm("tanh.approx.f32 %0, %1;" : "=f"(y) : "f"(x));
    return y;
}
// packed fp32x2 fma: d = a*b + d (elementwise on {lo,hi})
__device__ __forceinline__ void fma2(unsigned long long& d, unsigned long long a,
                                     unsigned long long b) {
    asm("fma.rn.f32x2 %0, %1, %2, %0;" : "+l"(d) : "l"(a), "l"(b));
}
__device__ __forceinline__ unsigned long long pack2(float lo, float hi) {
    unsigned long long r;
    asm("mov.b64 %0, {%1, %2};" : "=l"(r) : "f"(lo), "f"(hi));
    return r;
}
__device__ __forceinline__ void unpack2(unsigned long long v, float& lo, float& hi) {
    asm("mov.b64 {%0, %1}, %2;" : "=f"(lo), "=f"(hi) : "l"(v));
}
#define COMP(v, i) ((i) == 0 ? (v).x : (i) == 1 ? (v).y : (i) == 2 ? (v).z : (v).w)

// ================= graph conv (+tanh, +bn1), packed f32x2 =================
// Block = 32 atoms, 128 threads. Activations staged DUPLICATED ({v,v} pairs)
// in SMEM: [self-dup | sum-dup]. Each thread: 4 atoms x 4 output features,
// accumulators packed over feature pairs -> inner loop LDS.64 + 2x FFMA2.
template <int F, int D>
__global__ __launch_bounds__(128) void gc_kernel(
    const float* __restrict__ feat,
    const int* __restrict__ adj,
    const float* __restrict__ Ws,   // [F][64] slice for this degree
    const float* __restrict__ Wn,   // [F][64] slice (unused if D==0)
    const float* __restrict__ bias, // [64]
    const float* __restrict__ bn_g, const float* __restrict__ bn_b,
    const float* __restrict__ bn_m, const float* __restrict__ bn_v,
    float* __restrict__ out,
    int atom0, int cnt)
{
    constexpr int SUMO = (F == 75) ? 152 : 128;  // word offset of dup'd sum half
    constexpr int ROW  = (F == 75) ? 306 : 258;  // words/atom (pad: 4*ROW % 32 == 8)

    __shared__ __align__(16) float s_x[32 * ROW];
    __shared__ int s_adj[32][D > 0 ? D : 1];

    const int t    = threadIdx.x;
    const int ablk = blockIdx.x * 32;
    const int nat  = min(32, cnt - ablk);

    if (D > 0) {
        for (int idx = t; idx < nat * D; idx += 128) {
            int a = idx / D, m = idx - a * D;
            s_adj[a][m] = adj[(ablk + a) * D + m];
        }
        __syncthreads();
    }

    // ---- stage self + neighbor-sum, duplicated pairs (coalesced along k) ----
    for (int idx = t; idx < nat * F; idx += 128) {
        int a = idx / F, k = idx - a * F;
        int gi = atom0 + ablk + a;
        float v = feat[(size_t)gi * F + k];
        *(float2*)(s_x + a * ROW + 2 * k) = make_float2(v, v);
        if (D > 0) {
            float s = 0.f;
            #pragma unroll
            for (int m = 0; m < D; m++)
                s += feat[(size_t)s_adj[a][m] * F + k];
            *(float2*)(s_x + a * ROW + SUMO + 2 * k) = make_float2(s, s);
        }
    }
    __syncthreads();

    // ---- compute: 4 atoms x 4 features per thread, f32x2 packed ----
    const int j   = (t & 15) * 4;   // output feature quad
    const int grp = t >> 4;         // 8 groups x 4 atoms

    unsigned long long acc[4][2];
    {
        float4 b4 = *(const float4*)(bias + j);
        unsigned long long p0 = pack2(b4.x, b4.y);
        unsigned long long p1 = pack2(b4.z, b4.w);
        #pragma unroll
        for (int r = 0; r < 4; r++) { acc[r][0] = p0; acc[r][1] = p1; }
    }

    const float* xb = s_x + (grp * 4) * ROW;

    #pragma unroll 1
    for (int part = 0; part < (D > 0 ? 2 : 1); part++) {
        const float* __restrict__ W = part ? Wn : Ws;
        const float* xpb = xb + (part ? SUMO : 0);
        #pragma unroll 3
        for (int k = 0; k < F; k++) {
            ulonglong2 w2 = *(const ulonglong2*)(W + k * 64 + j);
            #pragma unroll
            for (int r = 0; r < 4; r++) {
                unsigned long long x2 =
                    *(const unsigned long long*)(xpb + r * ROW + 2 * k);
                fma2(acc[r][0], x2, w2.x);
                fma2(acc[r][1], x2, w2.y);
            }
        }
    }

    // ---- bn(tanh(acc)) and store ----
    float4 g4 = *(const float4*)(bn_g + j);
    float4 v4 = *(const float4*)(bn_v + j);
    float4 b4 = *(const float4*)(bn_b + j);
    float4 m4 = *(const float4*)(bn_m + j);
    float sc[4], sh[4];
    #pragma unroll
    for (int c = 0; c < 4; c++) {
        sc[c] = COMP(g4, c) * rsqrtf(COMP(v4, c) + 1e-3f);
        sh[c] = COMP(b4, c) - COMP(m4, c) * sc[c];
    }

    #pragma unroll
    for (int r = 0; r < 4; r++) {
        int a = grp * 4 + r;
        if (a < nat) {
            int gi = atom0 + ablk + a;
            float f0, f1, f2, f3;
            unpack2(acc[r][0], f0, f1);
            unpack2(acc[r][1], f2, f3);
            float4 o;
            o.x = sc[0] * tanh_fast(f0) + sh[0];
            o.y = sc[1] * tanh_fast(f1) + sh[1];
            o.z = sc[2] * tanh_fast(f2) + sh[2];
            o.w = sc[3] * tanh_fast(f3) + sh[3];
            *(float4*)(out + (size_t)gi * 64 + j) = o;
        }
    }
}

// ================= graph pool (float4) =================
__global__ __launch_bounds__(256) void pool_kernel(
    const float4* __restrict__ in, float4* __restrict__ out,
    const int* __restrict__ a1, const int* __restrict__ a2,
    const int* __restrict__ a3, const int* __restrict__ a4,
    const int* __restrict__ a5, const int* __restrict__ a6)
{
    int idx  = blockIdx.x * 256 + threadIdx.x;  // NA*16 total
    int atom = idx >> 4;
    int q    = idx & 15;
    float4 v = in[idx];

    if (atom >= 20000) {
        const int* ap; int d, li;
        if      (atom < 100000) { d = 1; ap = a1; li = atom - 20000;  }
        else if (atom < 250000) { d = 2; ap = a2; li = atom - 100000; }
        else if (atom < 400000) { d = 3; ap = a3; li = atom - 250000; }
        else if (atom < 475000) { d = 4; ap = a4; li = atom - 400000; }
        else if (atom < 495000) { d = 5; ap = a5; li = atom - 475000; }
        else                    { d = 6; ap = a6; li = atom - 495000; }
        for (int m = 0; m < d; m++) {
            int nb = ap[li * d + m];
            float4 u = in[nb * 16 + q];
            v.x = fmaxf(v.x, u.x); v.y = fmaxf(v.y, u.y);
            v.z = fmaxf(v.z, u.z); v.w = fmaxf(v.w, u.w);
        }
    }
    out[idx] = v;
}

// ================= dense1 [64]->[128] + tanh + bn3, fused gather, f32x2 =================
// Block = 32 atoms, 256 threads. Each thread: 4 atoms x 4 of 128 features.
__global__ __launch_bounds__(256) void dense1_gather_kernel(
    const float* __restrict__ in,
    const int* __restrict__ membership,
    const float* __restrict__ W,   // [64][128]
    const float* __restrict__ b,   // [128]
    const float* __restrict__ bn_g, const float* __restrict__ bn_b,
    const float* __restrict__ bn_m, const float* __restrict__ bn_v,
    float* __restrict__ gsum, unsigned* __restrict__ gmax,
    int cnt)
{
    constexpr int ROW = 130;  // 64 dup'd values + pad (4*ROW % 32 == 8)
    __shared__ __align__(16) float s_in[32 * ROW];
    __shared__ int s_mem[32];

    const int t    = threadIdx.x;
    const int ablk = blockIdx.x * 32;
    const int nat  = min(32, cnt - ablk);

    for (int idx = t; idx < nat * 16; idx += 256) {
        int a = idx >> 4, q = idx & 15;
        float4 u = *(const float4*)(in + (size_t)(ablk + a) * 64 + q * 4);
        float2* row = (float2*)(s_in + a * ROW) + q * 4;
        row[0] = make_float2(u.x, u.x);
        row[1] = make_float2(u.y, u.y);
        row[2] = make_float2(u.z, u.z);
        row[3] = make_float2(u.w, u.w);
    }
    if (t < nat) s_mem[t] = membership[ablk + t];
    __syncthreads();

    const int j   = (t & 31) * 4;   // 128 outputs
    const int grp = t >> 5;         // 8 groups x 4 atoms (warp-uniform -> broadcast)

    unsigned long long acc[4][2];
    {
        float4 b4 = *(const float4*)(b + j);
        unsigned long long p0 = pack2(b4.x, b4.y);
        unsigned long long p1 = pack2(b4.z, b4.w);
        #pragma unroll
        for (int r = 0; r < 4; r++) { acc[r][0] = p0; acc[r][1] = p1; }
    }

    const float* xb = s_in + (grp * 4) * ROW;
    #pragma unroll 4
    for (int k = 0; k < 64; k++) {
        ulonglong2 w2 = *(const ulonglong2*)(W + k * 128 + j);
        #pragma unroll
        for (int r = 0; r < 4; r++) {
            unsigned long long x2 = *(const unsigned long long*)(xb + r * ROW + 2 * k);
            fma2(acc[r][0], x2, w2.x);
            fma2(acc[r][1], x2, w2.y);
        }
    }

    float4 g4 = *(const float4*)(bn_g + j);
    float4 v4 = *(const float4*)(bn_v + j);
    float4 bb4 = *(const float4*)(bn_b + j);
    float4 m4 = *(const float4*)(bn_m + j);
    float sc[4], sh[4];
    #pragma unroll
    for (int c = 0; c < 4; c++) {
        sc[c] = COMP(g4, c) * rsqrtf(COMP(v4, c) + 1e-3f);
        sh[c] = COMP(bb4, c) - COMP(m4, c) * sc[c];
    }

    #pragma unroll
    for (int r = 0; r < 4; r++) {
        int a = grp * 4 + r;
        if (a < nat) {
            int m = s_mem[a];
            float f[4];
            unpack2(acc[r][0], f[0], f[1]);
            unpack2(acc[r][1], f[2], f[3]);
            #pragma unroll
            for (int c = 0; c < 4; c++) {
                float v = sc[c] * tanh_fast(f[c]) + sh[c];
                atomicAdd(&gsum[m * 128 + j + c], v);
                atomicMax(&gmax[m * 128 + j + c], enc_f(v));
            }
        }
    }
}

// ================= gather init =================
__global__ void init_gather_kernel(float* __restrict__ gsum, unsigned* __restrict__ gmax)
{
    int idx = blockIdx.x * 256 + threadIdx.x;
    if (idx < 1024 * 128) { gsum[idx] = 0.f; gmax[idx] = 0u; }
}

// ================= head: tanh(concat) -> sigmoid(dense 256->64) -> dense 64->1 =================
__global__ void head_kernel(const float* __restrict__ gsum, const unsigned* __restrict__ gmax,
                            const float* __restrict__ d2W, const float* __restrict__ d2b,
                            const float* __restrict__ d3W, const float* __restrict__ d3b,
                            float* __restrict__ out)
{
    __shared__ float sg[256];
    __shared__ float sred[64];
    const int row = blockIdx.x;
    const int t   = threadIdx.x;  // 64 threads

    for (int k = t; k < 256; k += 64) {
        float v = (k < 128) ? gsum[row * 128 + k] : dec_f(gmax[row * 128 + (k - 128)]);
        sg[k] = tanh_fast(v);
    }
    __syncthreads();

    float acc = d2b[t];
    for (int k = 0; k < 256; k++)
        acc = fmaf(sg[k], d2W[k * 64 + t], acc);
    float s = 1.f / (1.f + expf(-acc));

    sred[t] = s * d3W[t];
    __syncthreads();
    if (t < 32) {
        float x = sred[t] + sred[t + 32];
        #pragma unroll
        for (int off = 16; off; off >>= 1)
            x += __shfl_down_sync(0xffffffffu, x, off);
        if (t == 0) out[row] = x + d3b[0];
    }
}

// ================= dispatch helpers =================
template <int F>
static void launch_gc(int d, const float* feat, const int* adj,
                      const float* Ws, const float* Wn, const float* bias,
                      const float* bg, const float* bb, const float* bm, const float* bv,
                      float* out, int atom0, int cnt)
{
    dim3 grid((cnt + 31) / 32);
    switch (d) {
    case 0: gc_kernel<F,0><<<grid,128>>>(feat,adj,Ws,Wn,bias,bg,bb,bm,bv,out,atom0,cnt); break;
    case 1: gc_kernel<F,1><<<grid,128>>>(feat,adj,Ws,Wn,bias,bg,bb,bm,bv,out,atom0,cnt); break;
    case 2: gc_kernel<F,2><<<grid,128>>>(feat,adj,Ws,Wn,bias,bg,bb,bm,bv,out,atom0,cnt); break;
    case 3: gc_kernel<F,3><<<grid,128>>>(feat,adj,Ws,Wn,bias,bg,bb,bm,bv,out,atom0,cnt); break;
    case 4: gc_kernel<F,4><<<grid,128>>>(feat,adj,Ws,Wn,bias,bg,bb,bm,bv,out,atom0,cnt); break;
    case 5: gc_kernel<F,5><<<grid,128>>>(feat,adj,Ws,Wn,bias,bg,bb,bm,bv,out,atom0,cnt); break;
    case 6: gc_kernel<F,6><<<grid,128>>>(feat,adj,Ws,Wn,bias,bg,bb,bm,bv,out,atom0,cnt); break;
    }
}

// ================= launch =================
extern "C" void kernel_launch(void* const* d_in, const int* in_sizes, int n_in,
                              void* d_out, int out_size)
{
    const float* feat       = (const float*)d_in[0];
    const int*   membership = (const int*)d_in[1];
    const int*   adj[6]     = {(const int*)d_in[2], (const int*)d_in[3], (const int*)d_in[4],
                               (const int*)d_in[5], (const int*)d_in[6], (const int*)d_in[7]};
    const float* gc1_Wn = (const float*)d_in[8];
    const float* gc1_Ws = (const float*)d_in[9];
    const float* gc1_b  = (const float*)d_in[10];
    const float* gc2_Wn = (const float*)d_in[11];
    const float* gc2_Ws = (const float*)d_in[12];
    const float* gc2_b  = (const float*)d_in[13];
    const float* bn1g = (const float*)d_in[14];
    const float* bn1b = (const float*)d_in[15];
    const float* bn1m = (const float*)d_in[16];
    const float* bn1v = (const float*)d_in[17];
    const float* bn3g = (const float*)d_in[18];
    const float* bn3b = (const float*)d_in[19];
    const float* bn3m = (const float*)d_in[20];
    const float* bn3v = (const float*)d_in[21];
    const float* d1W = (const float*)d_in[22];
    const float* d1b = (const float*)d_in[23];
    const float* d2W = (const float*)d_in[24];
    const float* d2b = (const float*)d_in[25];
    const float* d3W = (const float*)d_in[26];
    const float* d3b = (const float*)d_in[27];

    float *h1, *h2, *gsum; unsigned* gmax;
    cudaGetSymbolAddress((void**)&h1, g_h1);
    cudaGetSymbolAddress((void**)&h2, g_h2);
    cudaGetSymbolAddress((void**)&gsum, g_gsum);
    cudaGetSymbolAddress((void**)&gmax, g_gmax);

    // ---- gc1 (+tanh +bn1): feat[NA,75] -> h1[NA,64]
    for (int d = 0; d <= 6; d++) {
        launch_gc<75>(d, feat, d ? adj[d - 1] : nullptr,
                      gc1_Ws + d * 75 * 64, d ? gc1_Wn + (d - 1) * 75 * 64 : nullptr,
                      gc1_b + d * 64, bn1g, bn1b, bn1m, bn1v,
                      h1, H_DEG_OFF[d], H_DEG_CNT[d]);
    }

    // ---- pool1: h1 -> h2
    pool_kernel<<<NA * 16 / 256, 256>>>((const float4*)h1, (float4*)h2,
                                        adj[0], adj[1], adj[2], adj[3], adj[4], adj[5]);

    // ---- gc2 (+tanh +bn1): h2[NA,64] -> h1[NA,64]
    for (int d = 0; d <= 6; d++) {
        launch_gc<64>(d, h2, d ? adj[d - 1] : nullptr,
                      gc2_Ws + d * 64 * 64, d ? gc2_Wn + (d - 1) * 64 * 64 : nullptr,
                      gc2_b + d * 64, bn1g, bn1b, bn1m, bn1v,
                      h1, H_DEG_OFF[d], H_DEG_CNT[d]);
    }

    // ---- pool2: h1 -> h2
    pool_kernel<<<NA * 16 / 256, 256>>>((const float4*)h1, (float4*)h2,
                                        adj[0], adj[1], adj[2], adj[3], adj[4], adj[5]);

    // ---- init gather accumulators, then fused dense1 + segment gather
    init_gather_kernel<<<(1024 * 128 + 255) / 256, 256>>>(gsum, gmax);
    dense1_gather_kernel<<<(NA + 31) / 32, 256>>>(h2, membership, d1W, d1b,
                                                  bn3g, bn3b, bn3m, bn3v,
                                                  gsum, gmax, NA);

    // ---- head
    head_kernel<<<1024, 64>>>(gsum, gmax, d2W, d2b, d3W, d3b, (float*)d_out);
}

// round 4
// speedup vs baseline: 1.2495x; 1.2495x over previous
#include <cuda_runtime.h>
#include <cuda_bf16.h>

// ---------------- problem constants ----------------
#define NA 500000
static const int H_DEG_CNT[7] = {20000, 80000, 150000, 150000, 75000, 20000, 5000};
static const int H_DEG_OFF[8] = {0, 20000, 100000, 250000, 400000, 475000, 495000, 500000};

// ---------------- scratch (device globals; no allocation allowed) ----------------
__device__ float    g_h1[(size_t)NA * 64];
__device__ float    g_h2[(size_t)NA * 64];
__device__ float    g_gsum[1024 * 128];
__device__ unsigned g_gmax[1024 * 128];

// ---------------- helpers ----------------
__device__ __forceinline__ unsigned enc_f(float f) {
    unsigned u = __float_as_uint(f);
    return (u >> 31) ? ~u : (u | 0x80000000u);
}
__device__ __forceinline__ float dec_f(unsigned u) {
    return (u >> 31) ? __uint_as_float(u & 0x7FFFFFFFu) : __uint_as_float(~u);
}
__device__ __forceinline__ float tanh_fast(float x) {
    float y;
    asm("tanh.approx.f32 %0, %1;" : "=f"(y) : "f"(x));
    return y;
}
#define COMP(v, i) ((i) == 0 ? (v).x : (i) == 1 ? (v).y : (i) == 2 ? (v).z : (v).w)

// ================= graph conv (+tanh, +bn1), warp-autonomous =================
// Each warp owns 8 atoms: gathers [self | neighbor-sum] into its private SMEM
// slice (no block barrier!), then computes 8 atoms x 2 features per lane.
template <int F, int D>
__global__ __launch_bounds__(256) void gc_kernel(
    const float* __restrict__ feat,
    const int* __restrict__ adj,
    const float* __restrict__ Ws,   // [F][64] slice for this degree
    const float* __restrict__ Wn,   // [F][64] slice (unused if D==0)
    const float* __restrict__ bias, // [64]
    const float* __restrict__ bn_g, const float* __restrict__ bn_b,
    const float* __restrict__ bn_m, const float* __restrict__ bn_v,
    float* __restrict__ out,
    int atom0, int cnt)
{
    constexpr int SUMO = (F == 75) ? 76 : 64;    // word offset of sum part (16B aligned)
    constexpr int ROW  = (F == 75) ? 152 : 128;  // words per atom
    constexpr int DD   = (D > 0) ? D : 1;

    __shared__ __align__(16) float s_x[8 * 8 * ROW];
    __shared__ int s_adj[8 * 8 * DD];

    const int t    = threadIdx.x;
    const int warp = t >> 5;
    const int lane = t & 31;
    const int abase = (blockIdx.x * 8 + warp) * 8;   // first atom of this warp's tile
    const int nat   = min(8, cnt - abase);

    float* sx   = s_x  + warp * 8 * ROW;
    int*   sadj = s_adj + warp * 8 * DD;

    if (nat > 0) {
        if (D > 0) {
            // adjacency rows for atoms [abase, abase+nat) are contiguous
            for (int u = lane; u < nat * D; u += 32)
                sadj[u] = adj[abase * D + u];
            __syncwarp();
        }
        // gather self + neighbor-sum (all loads independent -> high MLP)
        for (int u = lane; u < nat * F; u += 32) {
            int a = u / F, k = u - a * F;
            sx[a * ROW + k] = feat[(size_t)(atom0 + abase + a) * F + k];
            if (D > 0) {
                float s = 0.f;
                #pragma unroll
                for (int m = 0; m < D; m++)
                    s += feat[(size_t)sadj[a * D + m] * F + k];
                sx[a * ROW + SUMO + k] = s;
            }
        }
    }
    __syncwarp();
    if (nat <= 0) return;

    // ---- compute: 8 atoms x 2 features per lane ----
    const int j = lane * 2;

    float acc[8][2];
    {
        float2 b2 = *(const float2*)(bias + j);
        #pragma unroll
        for (int r = 0; r < 8; r++) { acc[r][0] = b2.x; acc[r][1] = b2.y; }
    }

    #pragma unroll 1
    for (int part = 0; part < (D > 0 ? 2 : 1); part++) {
        const float* __restrict__ W = part ? Wn : Ws;
        const float* xp = sx + (part ? SUMO : 0);
        int k0 = 0;
        #pragma unroll 2
        for (; k0 + 4 <= F; k0 += 4) {
            float2 w0 = *(const float2*)(W + (k0 + 0) * 64 + j);
            float2 w1 = *(const float2*)(W + (k0 + 1) * 64 + j);
            float2 w2 = *(const float2*)(W + (k0 + 2) * 64 + j);
            float2 w3 = *(const float2*)(W + (k0 + 3) * 64 + j);
            #pragma unroll
            for (int r = 0; r < 8; r++) {
                float4 x4 = *(const float4*)(xp + r * ROW + k0);
                acc[r][0] = fmaf(x4.x, w0.x, acc[r][0]);
                acc[r][1] = fmaf(x4.x, w0.y, acc[r][1]);
                acc[r][0] = fmaf(x4.y, w1.x, acc[r][0]);
                acc[r][1] = fmaf(x4.y, w1.y, acc[r][1]);
                acc[r][0] = fmaf(x4.z, w2.x, acc[r][0]);
                acc[r][1] = fmaf(x4.z, w2.y, acc[r][1]);
                acc[r][0] = fmaf(x4.w, w3.x, acc[r][0]);
                acc[r][1] = fmaf(x4.w, w3.y, acc[r][1]);
            }
        }
        for (; k0 < F; k0++) {  // tail (F=75)
            float2 w = *(const float2*)(W + k0 * 64 + j);
            #pragma unroll
            for (int r = 0; r < 8; r++) {
                float x = xp[r * ROW + k0];
                acc[r][0] = fmaf(x, w.x, acc[r][0]);
                acc[r][1] = fmaf(x, w.y, acc[r][1]);
            }
        }
    }

    // ---- bn(tanh(acc)) and store ----
    float2 g2 = *(const float2*)(bn_g + j);
    float2 v2 = *(const float2*)(bn_v + j);
    float2 b2 = *(const float2*)(bn_b + j);
    float2 m2 = *(const float2*)(bn_m + j);
    float sc0 = g2.x * rsqrtf(v2.x + 1e-3f);
    float sc1 = g2.y * rsqrtf(v2.y + 1e-3f);
    float sh0 = b2.x - m2.x * sc0;
    float sh1 = b2.y - m2.y * sc1;

    #pragma unroll
    for (int r = 0; r < 8; r++) {
        if (r < nat) {
            int gi = atom0 + abase + r;
            float2 o;
            o.x = sc0 * tanh_fast(acc[r][0]) + sh0;
            o.y = sc1 * tanh_fast(acc[r][1]) + sh1;
            *(float2*)(out + (size_t)gi * 64 + j) = o;
        }
    }
}

// ================= graph pool (float4) =================
__global__ __launch_bounds__(256) void pool_kernel(
    const float4* __restrict__ in, float4* __restrict__ out,
    const int* __restrict__ a1, const int* __restrict__ a2,
    const int* __restrict__ a3, const int* __restrict__ a4,
    const int* __restrict__ a5, const int* __restrict__ a6)
{
    int idx  = blockIdx.x * 256 + threadIdx.x;  // NA*16 total
    int atom = idx >> 4;
    int q    = idx & 15;
    float4 v = in[idx];

    if (atom >= 20000) {
        const int* ap; int d, li;
        if      (atom < 100000) { d = 1; ap = a1; li = atom - 20000;  }
        else if (atom < 250000) { d = 2; ap = a2; li = atom - 100000; }
        else if (atom < 400000) { d = 3; ap = a3; li = atom - 250000; }
        else if (atom < 475000) { d = 4; ap = a4; li = atom - 400000; }
        else if (atom < 495000) { d = 5; ap = a5; li = atom - 475000; }
        else                    { d = 6; ap = a6; li = atom - 495000; }
        for (int m = 0; m < d; m++) {
            int nb = ap[li * d + m];
            float4 u = in[nb * 16 + q];
            v.x = fmaxf(v.x, u.x); v.y = fmaxf(v.y, u.y);
            v.z = fmaxf(v.z, u.z); v.w = fmaxf(v.w, u.w);
        }
    }
    out[idx] = v;
}

// ================= dense1 [64]->[128] + tanh + bn3, fused segment gather =================
// Block = 64 atoms, 256 threads; each thread: 8 atoms x 4 features. (round-2 winner)
__global__ __launch_bounds__(256) void dense1_gather_kernel(
    const float* __restrict__ in,
    const int* __restrict__ membership,
    const float* __restrict__ W,   // [64][128]
    const float* __restrict__ b,   // [128]
    const float* __restrict__ bn_g, const float* __restrict__ bn_b,
    const float* __restrict__ bn_m, const float* __restrict__ bn_v,
    float* __restrict__ gsum, unsigned* __restrict__ gmax,
    int cnt)
{
    __shared__ float s_in[64][68];
    __shared__ int   s_mem[64];

    const int t    = threadIdx.x;
    const int ablk = blockIdx.x * 64;
    const int nat  = min(64, cnt - ablk);

    for (int idx = t; idx < nat * 16; idx += 256) {
        int a = idx >> 4, q = idx & 15;
        *(float4*)&s_in[a][q * 4] = *(const float4*)(in + (size_t)(ablk + a) * 64 + q * 4);
    }
    if (t < nat) s_mem[t] = membership[ablk + t];
    __syncthreads();

    const int j   = (t & 31) * 4;   // 128 outputs
    const int grp = t >> 5;         // 8 groups x 8 atoms

    float acc[8][4];
    {
        float4 b4 = *(const float4*)(b + j);
        #pragma unroll
        for (int r = 0; r < 8; r++) {
            acc[r][0] = b4.x; acc[r][1] = b4.y; acc[r][2] = b4.z; acc[r][3] = b4.w;
        }
    }

    for (int k0 = 0; k0 < 64; k0 += 4) {
        float4 w[4];
        #pragma unroll
        for (int kk = 0; kk < 4; kk++)
            w[kk] = *(const float4*)(W + (k0 + kk) * 128 + j);
        #pragma unroll
        for (int r = 0; r < 8; r++) {
            float4 xv = *(const float4*)&s_in[grp * 8 + r][k0];
            #pragma unroll
            for (int kk = 0; kk < 4; kk++) {
                float x = COMP(xv, kk);
                acc[r][0] = fmaf(x, w[kk].x, acc[r][0]);
                acc[r][1] = fmaf(x, w[kk].y, acc[r][1]);
                acc[r][2] = fmaf(x, w[kk].z, acc[r][2]);
                acc[r][3] = fmaf(x, w[kk].w, acc[r][3]);
            }
        }
    }

    float4 g4 = *(const float4*)(bn_g + j);
    float4 v4 = *(const float4*)(bn_v + j);
    float4 bb4 = *(const float4*)(bn_b + j);
    float4 m4 = *(const float4*)(bn_m + j);
    float sc[4], sh[4];
    #pragma unroll
    for (int c = 0; c < 4; c++) {
        sc[c] = COMP(g4, c) * rsqrtf(COMP(v4, c) + 1e-3f);
        sh[c] = COMP(bb4, c) - COMP(m4, c) * sc[c];
    }

    #pragma unroll
    for (int r = 0; r < 8; r++) {
        int a = grp * 8 + r;
        if (a < nat) {
            int m = s_mem[a];
            #pragma unroll
            for (int c = 0; c < 4; c++) {
                float v = sc[c] * tanh_fast(acc[r][c]) + sh[c];
                atomicAdd(&gsum[m * 128 + j + c], v);
                atomicMax(&gmax[m * 128 + j + c], enc_f(v));
            }
        }
    }
}

// ================= head: tanh(concat) -> sigmoid(dense 256->64) -> dense 64->1 =================
__global__ void head_kernel(const float* __restrict__ gsum, const unsigned* __restrict__ gmax,
                            const float* __restrict__ d2W, const float* __restrict__ d2b,
                            const float* __restrict__ d3W, const float* __restrict__ d3b,
                            float* __restrict__ out)
{
    __shared__ float sg[256];
    __shared__ float sred[64];
    const int row = blockIdx.x;
    const int t   = threadIdx.x;  // 64 threads

    for (int k = t; k < 256; k += 64) {
        float v = (k < 128) ? gsum[row * 128 + k] : dec_f(gmax[row * 128 + (k - 128)]);
        sg[k] = tanh_fast(v);
    }
    __syncthreads();

    float acc = d2b[t];
    for (int k = 0; k < 256; k++)
        acc = fmaf(sg[k], d2W[k * 64 + t], acc);
    float s = 1.f / (1.f + expf(-acc));

    sred[t] = s * d3W[t];
    __syncthreads();
    if (t < 32) {
        float x = sred[t] + sred[t + 32];
        #pragma unroll
        for (int off = 16; off; off >>= 1)
            x += __shfl_down_sync(0xffffffffu, x, off);
        if (t == 0) out[row] = x + d3b[0];
    }
}

// ================= dispatch helpers =================
template <int F>
static void launch_gc(int d, const float* feat, const int* adj,
                      const float* Ws, const float* Wn, const float* bias,
                      const float* bg, const float* bb, const float* bm, const float* bv,
                      float* out, int atom0, int cnt)
{
    dim3 grid((cnt + 63) / 64);
    switch (d) {
    case 0: gc_kernel<F,0><<<grid,256>>>(feat,adj,Ws,Wn,bias,bg,bb,bm,bv,out,atom0,cnt); break;
    case 1: gc_kernel<F,1><<<grid,256>>>(feat,adj,Ws,Wn,bias,bg,bb,bm,bv,out,atom0,cnt); break;
    case 2: gc_kernel<F,2><<<grid,256>>>(feat,adj,Ws,Wn,bias,bg,bb,bm,bv,out,atom0,cnt); break;
    case 3: gc_kernel<F,3><<<grid,256>>>(feat,adj,Ws,Wn,bias,bg,bb,bm,bv,out,atom0,cnt); break;
    case 4: gc_kernel<F,4><<<grid,256>>>(feat,adj,Ws,Wn,bias,bg,bb,bm,bv,out,atom0,cnt); break;
    case 5: gc_kernel<F,5><<<grid,256>>>(feat,adj,Ws,Wn,bias,bg,bb,bm,bv,out,atom0,cnt); break;
    case 6: gc_kernel<F,6><<<grid,256>>>(feat,adj,Ws,Wn,bias,bg,bb,bm,bv,out,atom0,cnt); break;
    }
}

// ================= launch =================
extern "C" void kernel_launch(void* const* d_in, const int* in_sizes, int n_in,
                              void* d_out, int out_size)
{
    const float* feat       = (const float*)d_in[0];
    const int*   membership = (const int*)d_in[1];
    const int*   adj[6]     = {(const int*)d_in[2], (const int*)d_in[3], (const int*)d_in[4],
                               (const int*)d_in[5], (const int*)d_in[6], (const int*)d_in[7]};
    const float* gc1_Wn = (const float*)d_in[8];
    const float* gc1_Ws = (const float*)d_in[9];
    const float* gc1_b  = (const float*)d_in[10];
    const float* gc2_Wn = (const float*)d_in[11];
    const float* gc2_Ws = (const float*)d_in[12];
    const float* gc2_b  = (const float*)d_in[13];
    const float* bn1g = (const float*)d_in[14];
    const float* bn1b = (const float*)d_in[15];
    const float* bn1m = (const float*)d_in[16];
    const float* bn1v = (const float*)d_in[17];
    const float* bn3g = (const float*)d_in[18];
    const float* bn3b = (const float*)d_in[19];
    const float* bn3m = (const float*)d_in[20];
    const float* bn3v = (const float*)d_in[21];
    const float* d1W = (const float*)d_in[22];
    const float* d1b = (const float*)d_in[23];
    const float* d2W = (const float*)d_in[24];
    const float* d2b = (const float*)d_in[25];
    const float* d3W = (const float*)d_in[26];
    const float* d3b = (const float*)d_in[27];

    float *h1, *h2, *gsum; unsigned* gmax;
    cudaGetSymbolAddress((void**)&h1, g_h1);
    cudaGetSymbolAddress((void**)&h2, g_h2);
    cudaGetSymbolAddress((void**)&gsum, g_gsum);
    cudaGetSymbolAddress((void**)&gmax, g_gmax);

    // ---- gc1 (+tanh +bn1): feat[NA,75] -> h1[NA,64]
    for (int d = 0; d <= 6; d++) {
        launch_gc<75>(d, feat, d ? adj[d - 1] : nullptr,
                      gc1_Ws + d * 75 * 64, d ? gc1_Wn + (d - 1) * 75 * 64 : nullptr,
                      gc1_b + d * 64, bn1g, bn1b, bn1m, bn1v,
                      h1, H_DEG_OFF[d], H_DEG_CNT[d]);
    }

    // ---- pool1: h1 -> h2
    pool_kernel<<<NA * 16 / 256, 256>>>((const float4*)h1, (float4*)h2,
                                        adj[0], adj[1], adj[2], adj[3], adj[4], adj[5]);

    // ---- gc2 (+tanh +bn1): h2[NA,64] -> h1[NA,64]
    for (int d = 0; d <= 6; d++) {
        launch_gc<64>(d, h2, d ? adj[d - 1] : nullptr,
                      gc2_Ws + d * 64 * 64, d ? gc2_Wn + (d - 1) * 64 * 64 : nullptr,
                      gc2_b + d * 64, bn1g, bn1b, bn1m, bn1v,
                      h1, H_DEG_OFF[d], H_DEG_CNT[d]);
    }

    // ---- pool2: h1 -> h2
    pool_kernel<<<NA * 16 / 256, 256>>>((const float4*)h1, (float4*)h2,
                                        adj[0], adj[1], adj[2], adj[3], adj[4], adj[5]);

    // ---- zero gather accumulators (graph-capturable memsets), then fused dense1+gather
    cudaMemsetAsync(gsum, 0, 1024 * 128 * sizeof(float));
    cudaMemsetAsync(gmax, 0, 1024 * 128 * sizeof(unsigned));
    dense1_gather_kernel<<<(NA + 63) / 64, 256>>>(h2, membership, d1W, d1b,
                                                  bn3g, bn3b, bn3m, bn3v,
                                                  gsum, gmax, NA);

    // ---- head
    head_kernel<<<1024, 64>>>(gsum, gmax, d2W, d2b, d3W, d3b, (float*)d_out);
}